// round 16
// baseline (speedup 1.0000x reference)
#include <cuda.h>
#include <cuda_runtime.h>
#include <cuda_fp16.h>
#include <stdint.h>

#define DIM_  2048
#define HID_  2048
#define NH_   4
#define HD_   512
#define B_    4
#define L_    2048
#define NTOK_ 8192
#define GN_   8192
#define EPS_  1e-6f
#define CH_   64
#define NCH_  32
#define BH_   16
#define BHD_  (BH_*HD_)
#define KROW_ 2048

// ---------------- device scratch ----------------
__device__ __align__(1024) __half g_xh[(size_t)NTOK_*DIM_];
__device__ __align__(1024) __half g_Wih[(size_t)HID_*DIM_];
__device__ __align__(1024) __half g_Wgh[(size_t)GN_*HID_];
__device__ __align__(1024) __half g_Woh[(size_t)DIM_*HID_];
__device__ __align__(1024) __half g_xph[(size_t)NTOK_*HID_];
__device__ __align__(1024) __half g_gates[(size_t)NTOK_*GN_];   // activated gates, fp16
__device__ __align__(1024) __half g_hh[(size_t)NTOK_*HID_];
__device__ float g_scanA[NCH_*BHD_], g_scanB[NCH_*BHD_], g_carry[NCH_*BHD_];

// ---------------- helpers ----------------
__device__ __forceinline__ uint32_t smem_u32(const void* p){
    uint32_t a;
    asm("{ .reg .u64 t; cvta.to.shared.u64 t, %1; cvt.u32.u64 %0, t; }" : "=r"(a) : "l"(p));
    return a;
}

#define MBARRIER_INIT(a, cnt) \
    asm volatile("mbarrier.init.shared.b64 [%0], %1;" :: "r"(a), "r"(cnt) : "memory")
#define MBARRIER_EXPECT_TX(a, tx) \
    asm volatile("mbarrier.arrive.expect_tx.shared.b64 _, [%0], %1;" :: "r"(a), "r"(tx) : "memory")
#define MBARRIER_ARRIVE(a) \
    asm volatile("mbarrier.arrive.shared.b64 _, [%0];" :: "r"(a) : "memory")
#define FENCE_PROXY_ASYNC() \
    asm volatile("fence.proxy.async.shared::cta;" ::: "memory")

__device__ __forceinline__ void bar_wait(uint32_t mbar, uint32_t parity){
    asm volatile("{\n\t.reg .pred P;\n\t"
        "W_%=:\n\t"
        "mbarrier.try_wait.parity.shared.b64 P, [%0], %1;\n\t"
        "@!P bra W_%=;\n\t}"
        :: "r"(mbar), "r"(parity) : "memory");
}

#define TMA2D(dst, map, x, y, mbar) \
    asm volatile("cp.async.bulk.tensor.2d.shared::cta.global.tile.mbarrier::complete_tx::bytes " \
        "[%0], [%1, {%2, %3}], [%4];" \
        :: "r"(dst), "l"(map), "r"(x), "r"(y), "r"(mbar) : "memory")

__device__ __forceinline__ void ldsm4(uint32_t& r0, uint32_t& r1, uint32_t& r2, uint32_t& r3, uint32_t a){
    asm volatile("ldmatrix.sync.aligned.m8n8.x4.shared.b16 {%0,%1,%2,%3}, [%4];"
        : "=r"(r0), "=r"(r1), "=r"(r2), "=r"(r3) : "r"(a));
}
__device__ __forceinline__ void mma_h(float* d, const uint32_t* a, const uint32_t* b){
    asm volatile("mma.sync.aligned.m16n8k16.row.col.f32.f16.f16.f32 "
        "{%0,%1,%2,%3},{%4,%5,%6,%7},{%8,%9},{%0,%1,%2,%3};"
        : "+f"(d[0]), "+f"(d[1]), "+f"(d[2]), "+f"(d[3])
        : "r"(a[0]), "r"(a[1]), "r"(a[2]), "r"(a[3]), "r"(b[0]), "r"(b[1]));
}

// ---------------- convert fp32 -> fp16 ----------------
__global__ void to16(const float* __restrict__ src, __half* __restrict__ dst, int n4){
    int i = blockIdx.x*blockDim.x + threadIdx.x;
    if (i >= n4) return;
    float4 v = ((const float4*)src)[i];
    __half2* D = (__half2*)dst;
    D[2*i]   = __halves2half2(__float2half_rn(v.x), __float2half_rn(v.y));
    D[2*i+1] = __halves2half2(__float2half_rn(v.z), __float2half_rn(v.w));
}

// ---------------- TMA-fed fp16 HMMA GEMM: C[M,N] = A[M,K]*B[N,K]^T ----------------
// CTA tile 128x128, BK=64 fp16 (128B rows, SW128), 8 warps (32x64), occ 2, 3-stage TMA ring.
// Producer-consumer mbarrier pipeline (no block-wide sync in mainloop); the generic->async
// proxy edge (consumer ldsm -> TMA refill) is ordered by fence.proxy.async on the producer.
#define A_PL 16384
#define STG_B (2*A_PL)      // 32768: A + B
#define NSTG 3
#define CTRL 1024
#define GSMEM (CTRL + NSTG*STG_B)   // 99328

__device__ __forceinline__ float gate_act(float v, int g){
    if (g == 0) return __expf(v);
    if (g == 3) return tanhf(v);
    return 1.f/(1.f + __expf(-v));
}

__global__ void __launch_bounds__(256, 2) gemm_f16(
    const __grid_constant__ CUtensorMap tA, const __grid_constant__ CUtensorMap tB,
    const float* __restrict__ bias, float* __restrict__ Cf,
    __half* __restrict__ Ch,
    int N, int KT, int mode)   // mode 0: fp16 out; 1: bias+gate-act fp16 out; 2: fp32 out
{
    extern __shared__ char smem[];
    uint32_t sb = smem_u32(smem);
    const int tid = threadIdx.x;
    const int bm = blockIdx.y, bn = blockIdx.x;

    // barriers: full[s] at sb + 8*s, empty[s] at sb + 64 + 8*s
    if (tid == 0){
        #pragma unroll
        for (int s = 0; s < NSTG; s++){
            MBARRIER_INIT(sb + 8*s, 1);
            MBARRIER_INIT(sb + 64 + 8*s, 256);
        }
    }
    __syncthreads();
    if (tid == 0){
        #pragma unroll
        for (int st = 0; st < NSTG; st++){
            MBARRIER_EXPECT_TX(sb + 8*st, STG_B);
            uint32_t base = sb + CTRL + st*STG_B;
            TMA2D(base,        &tA, st*64, bm*128, sb + 8*st);
            TMA2D(base + A_PL, &tB, st*64, bn*128, sb + 8*st);
        }
    }

    const int warp = tid >> 5, ln = tid & 31;
    const int wm = warp >> 1, wn = warp & 1;

    float acc[2][8][4];
    #pragma unroll
    for (int a = 0; a < 2; a++)
        #pragma unroll
        for (int b = 0; b < 8; b++)
            #pragma unroll
            for (int q = 0; q < 4; q++) acc[a][b][q] = 0.f;

    int st = 0, ph = 0;

    for (int kt = 0; kt < KT; kt++){
        bar_wait(sb + 8*st, ph);

        const uint32_t aB = sb + CTRL + st*STG_B;
        const uint32_t bB = aB + A_PL;

        #pragma unroll
        for (int ks = 0; ks < 4; ks++){
            uint32_t af[2][4];
            #pragma unroll
            for (int mt = 0; mt < 2; mt++){
                uint32_t row = wm*32 + mt*16 + ((ln >> 3) & 1)*8 + (ln & 7);
                uint32_t off = row*128 + (ks*16 + (ln >> 4)*8)*2;
                off ^= (off >> 3) & 0x70;
                ldsm4(af[mt][0], af[mt][1], af[mt][2], af[mt][3], aB + off);
            }
            uint32_t bf[8][2];
            #pragma unroll
            for (int p = 0; p < 4; p++){
                uint32_t row = wn*64 + p*16 + (ln >> 4)*8 + (ln & 7);
                uint32_t off = row*128 + (ks*16 + ((ln >> 3) & 1)*8)*2;
                off ^= (off >> 3) & 0x70;
                uint32_t r0, r1, r2, r3;
                ldsm4(r0, r1, r2, r3, bB + off);
                bf[2*p][0] = r0; bf[2*p][1] = r1; bf[2*p+1][0] = r2; bf[2*p+1][1] = r3;
            }
            #pragma unroll
            for (int mt = 0; mt < 2; mt++)
                #pragma unroll
                for (int nt = 0; nt < 8; nt++)
                    mma_h(acc[mt][nt], af[mt], bf[nt]);
        }
        // consumer done with this stage's SMEM (all ldsm consumed by issued MMAs)
        MBARRIER_ARRIVE(sb + 64 + 8*st);
        if (tid == 0 && kt + NSTG < KT){
            bar_wait(sb + 64 + 8*st, ph);      // all 256 consumed
            FENCE_PROXY_ASYNC();               // order generic reads before async-proxy TMA write
            MBARRIER_EXPECT_TX(sb + 8*st, STG_B);
            uint32_t base = sb + CTRL + st*STG_B;
            TMA2D(base,        &tA, (kt+NSTG)*64, bm*128, sb + 8*st);
            TMA2D(base + A_PL, &tB, (kt+NSTG)*64, bn*128, sb + 8*st);
        }
        if (++st == NSTG){ st = 0; ph ^= 1; }
    }

    // ---- epilogue ----
    const int orow = bm*128 + wm*32;
    const int ocol = bn*128 + wn*64;
    #pragma unroll
    for (int mt = 0; mt < 2; mt++)
        #pragma unroll
        for (int nt = 0; nt < 8; nt++){
            float* a = acc[mt][nt];
            int r0 = orow + mt*16 + (ln >> 2);
            int c0 = ocol + nt*8 + (ln & 3)*2;
            if (mode == 0){
                #pragma unroll
                for (int q = 0; q < 2; q++){
                    size_t o = (size_t)(r0 + q*8)*N + c0;
                    *(__half2*)(Ch + o) = __halves2half2(
                        __float2half_rn(a[2*q]), __float2half_rn(a[2*q+1]));
                }
            } else if (mode == 1){
                int g = (c0 >> 9) & 3;
                float b0 = bias[c0], b1 = bias[c0+1];
                float v00 = gate_act(a[0] + b0, g), v01 = gate_act(a[1] + b1, g);
                float v10 = gate_act(a[2] + b0, g), v11 = gate_act(a[3] + b1, g);
                *(__half2*)(Ch + (size_t)r0*N + c0) =
                    __halves2half2(__float2half_rn(v00), __float2half_rn(v01));
                *(__half2*)(Ch + (size_t)(r0+8)*N + c0) =
                    __halves2half2(__float2half_rn(v10), __float2half_rn(v11));
            } else {
                *(float2*)(Cf + (size_t)r0*N + c0)     = float2{a[0], a[1]};
                *(float2*)(Cf + (size_t)(r0+8)*N + c0) = float2{a[2], a[3]};
            }
        }
}

// ---------------- scan pass 1: per-chunk (A = prod f, B) — gates pre-activated fp16 ----------------
__global__ void scan_pass1(){
    int blk = blockIdx.x;
    int ch = blk / BH_, bh = blk % BH_;
    int b = bh / NH_, h = bh % NH_;
    int d = threadIdx.x;
    float A = 1.f, Bv = 0.f;
    for (int s = 0; s < CH_; s++){
        int tok = b*L_ + ch*CH_ + s;
        size_t base = (size_t)tok*GN_ + h*(4*HD_) + d;
        float ig = __half2float(g_gates[base]);
        float f  = __half2float(g_gates[base + HD_]);
        float cd = __half2float(g_gates[base + 3*HD_]);
        Bv = f*Bv + ig*cd;
        A *= f;
    }
    g_scanA[ch*BHD_ + bh*HD_ + d] = A;
    g_scanB[ch*BHD_ + bh*HD_ + d] = Bv;
}

// ---------------- scan pass 2: sequential chunk composition ----------------
__global__ void scan_pass2(){
    int idx = blockIdx.x*blockDim.x + threadIdx.x;
    float c = 0.f;
    for (int ch = 0; ch < NCH_; ch++){
        g_carry[ch*BHD_ + idx] = c;
        c = g_scanA[ch*BHD_ + idx]*c + g_scanB[ch*BHD_ + idx];
    }
}

// ---------------- scan pass 3: replay + RMS norm + h (fp16 out), 1 sync/step ----------------
__global__ void scan_pass3(const float* __restrict__ rms_w){
    __shared__ float red[2][16];
    int blk = blockIdx.x;
    int ch = blk / BH_, bh = blk % BH_;
    int b = bh / NH_, h = bh % NH_;
    int d = threadIdx.x;
    int warp = d >> 5, lane = d & 31;
    float c = g_carry[ch*BHD_ + bh*HD_ + d];
    float w = rms_w[d];
    for (int s = 0; s < CH_; s++){
        int tok = b*L_ + ch*CH_ + s;
        size_t base = (size_t)tok*GN_ + h*(4*HD_) + d;
        float ig = __half2float(g_gates[base]);
        float f  = __half2float(g_gates[base + HD_]);
        float og = __half2float(g_gates[base + 2*HD_]);
        float cd = __half2float(g_gates[base + 3*HD_]);
        c = f*c + ig*cd;
        float sq = c*c;
        #pragma unroll
        for (int o = 16; o; o >>= 1) sq += __shfl_xor_sync(0xffffffffu, sq, o);
        int par = s & 1;
        if (!lane) red[par][warp] = sq;
        __syncthreads();
        float tot = 0.f;
        #pragma unroll
        for (int i = 0; i < 16; i++) tot += red[par][i];
        float s_norm = rsqrtf(tot*(1.f/HD_) + EPS_);
        float cn = c * s_norm * w;
        float hv = og * tanhf(cn);
        g_hh[(size_t)tok*HID_ + h*HD_ + d] = __float2half_rn(hv);
    }
}

// ---------------- host side ----------------
typedef CUresult (*PFN_encode_t)(CUtensorMap*, CUtensorMapDataType, cuuint32_t, void*,
                                 const cuuint64_t*, const cuuint64_t*, const cuuint32_t*,
                                 const cuuint32_t*, CUtensorMapInterleave, CUtensorMapSwizzle,
                                 CUtensorMapL2promotion, CUtensorMapFloatOOBfill);

static void enc_map16(PFN_encode_t fn, CUtensorMap* m, void* gaddr, uint64_t rows){
    cuuint64_t dims[2]    = {KROW_, rows};
    cuuint64_t strides[1] = {KROW_ * 2};
    cuuint32_t box[2]     = {64u, 128u};
    cuuint32_t es[2]      = {1u, 1u};
    fn(m, CU_TENSOR_MAP_DATA_TYPE_FLOAT16, 2, gaddr, dims, strides, box, es,
       CU_TENSOR_MAP_INTERLEAVE_NONE, CU_TENSOR_MAP_SWIZZLE_128B,
       CU_TENSOR_MAP_L2_PROMOTION_L2_128B, CU_TENSOR_MAP_FLOAT_OOB_FILL_NONE);
}

extern "C" void kernel_launch(void* const* d_in, const int* in_sizes, int n_in,
                              void* d_out, int out_size){
    const float* x      = (const float*)d_in[0];
    const float* W_in   = (const float*)d_in[1];
    const float* W_gate = (const float*)d_in[2];
    const float* b_gate = (const float*)d_in[3];
    const float* rms_w  = (const float*)d_in[4];
    const float* W_out  = (const float*)d_in[5];

    void *xh, *wih, *wgh, *woh, *xph, *gts, *hh;
    cudaGetSymbolAddress(&xh,  g_xh);
    cudaGetSymbolAddress(&wih, g_Wih);  cudaGetSymbolAddress(&wgh, g_Wgh);
    cudaGetSymbolAddress(&woh, g_Woh);
    cudaGetSymbolAddress(&xph, g_xph);
    cudaGetSymbolAddress(&gts, g_gates);
    cudaGetSymbolAddress(&hh,  g_hh);

    void* pfn = nullptr;
    cudaDriverEntryPointQueryResult qr;
    cudaGetDriverEntryPoint("cuTensorMapEncodeTiled", &pfn, cudaEnableDefault, &qr);
    PFN_encode_t enc = (PFN_encode_t)pfn;

    CUtensorMap mX, mWi, mXp, mWg, mH, mWo;
    enc_map16(enc, &mX,  xh,  NTOK_);
    enc_map16(enc, &mWi, wih, HID_);
    enc_map16(enc, &mXp, xph, NTOK_);
    enc_map16(enc, &mWg, wgh, GN_);
    enc_map16(enc, &mH,  hh,  NTOK_);
    enc_map16(enc, &mWo, woh, DIM_);

    cudaFuncSetAttribute(gemm_f16, cudaFuncAttributeMaxDynamicSharedMemorySize, GSMEM);

    int n4;
    n4 = NTOK_*DIM_/4; to16<<<(n4+255)/256, 256>>>(x,      (__half*)xh,  n4);  // 0
    n4 = HID_*DIM_/4;  to16<<<(n4+255)/256, 256>>>(W_in,   (__half*)wih, n4);  // 1
    n4 = GN_*HID_/4;   to16<<<(n4+255)/256, 256>>>(W_gate, (__half*)wgh, n4);  // 2

    // 3: G1: xp = x @ W_in^T -> fp16   (profiled slot)
    gemm_f16<<<dim3(HID_/128, NTOK_/128), 256, GSMEM>>>(
        mX, mWi, nullptr, nullptr, (__half*)xph, HID_, KROW_/64, 0);

    n4 = DIM_*HID_/4;  to16<<<(n4+255)/256, 256>>>(W_out, (__half*)woh, n4);   // 4

    // G2: gates = act(xp @ W_gate^T + b_gate) -> fp16
    gemm_f16<<<dim3(GN_/128, NTOK_/128), 256, GSMEM>>>(
        mXp, mWg, b_gate, nullptr, (__half*)gts, GN_, KROW_/64, 1);

    // chunked parallel scan
    scan_pass1<<<NCH_*BH_, HD_>>>();
    scan_pass2<<<BHD_/256, 256>>>();
    scan_pass3<<<NCH_*BH_, HD_>>>(rms_w);

    // G3: out = h @ W_out^T -> fp32 to d_out
    gemm_f16<<<dim3(DIM_/128, NTOK_/128), 256, GSMEM>>>(
        mH, mWo, nullptr, (float*)d_out, nullptr, DIM_, KROW_/64, 2);
}

// round 17
// speedup vs baseline: 1.0089x; 1.0089x over previous
#include <cuda.h>
#include <cuda_runtime.h>
#include <cuda_fp16.h>
#include <stdint.h>

#define DIM_  2048
#define HID_  2048
#define NH_   4
#define HD_   512
#define B_    4
#define L_    2048
#define NTOK_ 8192
#define GN_   8192
#define EPS_  1e-6f
#define CH_   64
#define NCH_  32
#define BH_   16
#define BHD_  (BH_*HD_)
#define KROW_ 2048

// ---------------- device scratch ----------------
__device__ __align__(1024) __half g_xh[(size_t)NTOK_*DIM_];
__device__ __align__(1024) __half g_Wih[(size_t)HID_*DIM_];
__device__ __align__(1024) __half g_Wgh[(size_t)GN_*HID_];
__device__ __align__(1024) __half g_Woh[(size_t)DIM_*HID_];
__device__ __align__(1024) __half g_xph[(size_t)NTOK_*HID_];
__device__ __align__(1024) __half g_gates[(size_t)NTOK_*GN_];   // activated gates, fp16
__device__ __align__(1024) __half g_hh[(size_t)NTOK_*HID_];
__device__ float g_scanA[NCH_*BHD_], g_scanB[NCH_*BHD_], g_carry[NCH_*BHD_];

// ---------------- helpers ----------------
__device__ __forceinline__ uint32_t smem_u32(const void* p){
    uint32_t a;
    asm("{ .reg .u64 t; cvta.to.shared.u64 t, %1; cvt.u32.u64 %0, t; }" : "=r"(a) : "l"(p));
    return a;
}

#define MBARRIER_INIT(a, cnt) \
    asm volatile("mbarrier.init.shared.b64 [%0], %1;" :: "r"(a), "r"(cnt) : "memory")
#define MBARRIER_EXPECT_TX(a, tx) \
    asm volatile("mbarrier.arrive.expect_tx.shared.b64 _, [%0], %1;" :: "r"(a), "r"(tx) : "memory")
#define MBARRIER_ARRIVE(a) \
    asm volatile("mbarrier.arrive.shared.b64 _, [%0];" :: "r"(a) : "memory")
#define FENCE_PROXY_ASYNC() \
    asm volatile("fence.proxy.async.shared::cta;" ::: "memory")

__device__ __forceinline__ void bar_wait(uint32_t mbar, uint32_t parity){
    asm volatile("{\n\t.reg .pred P;\n\t"
        "W_%=:\n\t"
        "mbarrier.try_wait.parity.shared.b64 P, [%0], %1;\n\t"
        "@!P bra W_%=;\n\t}"
        :: "r"(mbar), "r"(parity) : "memory");
}

#define TMA2D(dst, map, x, y, mbar) \
    asm volatile("cp.async.bulk.tensor.2d.shared::cta.global.tile.mbarrier::complete_tx::bytes " \
        "[%0], [%1, {%2, %3}], [%4];" \
        :: "r"(dst), "l"(map), "r"(x), "r"(y), "r"(mbar) : "memory")

__device__ __forceinline__ void ldsm4(uint32_t& r0, uint32_t& r1, uint32_t& r2, uint32_t& r3, uint32_t a){
    asm volatile("ldmatrix.sync.aligned.m8n8.x4.shared.b16 {%0,%1,%2,%3}, [%4];"
        : "=r"(r0), "=r"(r1), "=r"(r2), "=r"(r3) : "r"(a));
}
__device__ __forceinline__ void mma_h(float* d, const uint32_t* a, const uint32_t* b){
    asm volatile("mma.sync.aligned.m16n8k16.row.col.f32.f16.f16.f32 "
        "{%0,%1,%2,%3},{%4,%5,%6,%7},{%8,%9},{%0,%1,%2,%3};"
        : "+f"(d[0]), "+f"(d[1]), "+f"(d[2]), "+f"(d[3])
        : "r"(a[0]), "r"(a[1]), "r"(a[2]), "r"(a[3]), "r"(b[0]), "r"(b[1]));
}

// ---------------- convert fp32 -> fp16 ----------------
__global__ void to16(const float* __restrict__ src, __half* __restrict__ dst, int n4){
    int i = blockIdx.x*blockDim.x + threadIdx.x;
    if (i >= n4) return;
    float4 v = ((const float4*)src)[i];
    __half2* D = (__half2*)dst;
    D[2*i]   = __halves2half2(__float2half_rn(v.x), __float2half_rn(v.y));
    D[2*i+1] = __halves2half2(__float2half_rn(v.z), __float2half_rn(v.w));
}

// ---------------- TMA-fed fp16 HMMA GEMM: C[M,N] = A[M,K]*B[N,K]^T ----------------
// CTA tile 128x128, BK=64 fp16 (128B rows, SW128), 8 warps (32x64), occ 2, 3-stage TMA ring.
// Producer-consumer mbarrier pipeline: empty[s] has count 8 — ONE arrival per warp (lane 0),
// issued right after the warp's LAST ldsm of the stage (before its final MMAs), so the TMA
// refill overlaps the tail of the compute. Proxy fence orders ldsm -> TMA refill.
#define A_PL 16384
#define STG_B (2*A_PL)      // 32768: A + B
#define NSTG 3
#define CTRL 1024
#define GSMEM (CTRL + NSTG*STG_B)   // 99328

__device__ __forceinline__ float gate_act(float v, int g){
    if (g == 0) return __expf(v);
    if (g == 3) return tanhf(v);
    return 1.f/(1.f + __expf(-v));
}

__global__ void __launch_bounds__(256, 2) gemm_f16(
    const __grid_constant__ CUtensorMap tA, const __grid_constant__ CUtensorMap tB,
    const float* __restrict__ bias, float* __restrict__ Cf,
    __half* __restrict__ Ch,
    int N, int KT, int mode)   // mode 0: fp16 out; 1: bias+gate-act fp16 out; 2: fp32 out
{
    extern __shared__ char smem[];
    uint32_t sb = smem_u32(smem);
    const int tid = threadIdx.x;
    const int bm = blockIdx.y, bn = blockIdx.x;

    // barriers: full[s] at sb + 8*s, empty[s] at sb + 64 + 8*s (count 8: one per warp)
    if (tid == 0){
        #pragma unroll
        for (int s = 0; s < NSTG; s++){
            MBARRIER_INIT(sb + 8*s, 1);
            MBARRIER_INIT(sb + 64 + 8*s, 8);
        }
    }
    __syncthreads();
    if (tid == 0){
        #pragma unroll
        for (int st = 0; st < NSTG; st++){
            MBARRIER_EXPECT_TX(sb + 8*st, STG_B);
            uint32_t base = sb + CTRL + st*STG_B;
            TMA2D(base,        &tA, st*64, bm*128, sb + 8*st);
            TMA2D(base + A_PL, &tB, st*64, bn*128, sb + 8*st);
        }
    }

    const int warp = tid >> 5, ln = tid & 31;
    const int wm = warp >> 1, wn = warp & 1;

    float acc[2][8][4];
    #pragma unroll
    for (int a = 0; a < 2; a++)
        #pragma unroll
        for (int b = 0; b < 8; b++)
            #pragma unroll
            for (int q = 0; q < 4; q++) acc[a][b][q] = 0.f;

    int st = 0, ph = 0;

    for (int kt = 0; kt < KT; kt++){
        bar_wait(sb + 8*st, ph);

        const uint32_t aB = sb + CTRL + st*STG_B;
        const uint32_t bB = aB + A_PL;

        #pragma unroll
        for (int ks = 0; ks < 4; ks++){
            uint32_t af[2][4];
            #pragma unroll
            for (int mt = 0; mt < 2; mt++){
                uint32_t row = wm*32 + mt*16 + ((ln >> 3) & 1)*8 + (ln & 7);
                uint32_t off = row*128 + (ks*16 + (ln >> 4)*8)*2;
                off ^= (off >> 3) & 0x70;
                ldsm4(af[mt][0], af[mt][1], af[mt][2], af[mt][3], aB + off);
            }
            uint32_t bf[8][2];
            #pragma unroll
            for (int p = 0; p < 4; p++){
                uint32_t row = wn*64 + p*16 + (ln >> 4)*8 + (ln & 7);
                uint32_t off = row*128 + (ks*16 + ((ln >> 3) & 1)*8)*2;
                off ^= (off >> 3) & 0x70;
                uint32_t r0, r1, r2, r3;
                ldsm4(r0, r1, r2, r3, bB + off);
                bf[2*p][0] = r0; bf[2*p][1] = r1; bf[2*p+1][0] = r2; bf[2*p+1][1] = r3;
            }
            // after the warp's final ldsm of this stage, release it (fragments are in regs)
            if (ks == 3 && ln == 0) MBARRIER_ARRIVE(sb + 64 + 8*st);
            #pragma unroll
            for (int mt = 0; mt < 2; mt++)
                #pragma unroll
                for (int nt = 0; nt < 8; nt++)
                    mma_h(acc[mt][nt], af[mt], bf[nt]);
        }
        if (tid == 0 && kt + NSTG < KT){
            bar_wait(sb + 64 + 8*st, ph);      // all 8 warps released the stage
            FENCE_PROXY_ASYNC();               // order generic reads before async-proxy TMA write
            MBARRIER_EXPECT_TX(sb + 8*st, STG_B);
            uint32_t base = sb + CTRL + st*STG_B;
            TMA2D(base,        &tA, (kt+NSTG)*64, bm*128, sb + 8*st);
            TMA2D(base + A_PL, &tB, (kt+NSTG)*64, bn*128, sb + 8*st);
        }
        if (++st == NSTG){ st = 0; ph ^= 1; }
    }

    // ---- epilogue ----
    const int orow = bm*128 + wm*32;
    const int ocol = bn*128 + wn*64;
    #pragma unroll
    for (int mt = 0; mt < 2; mt++)
        #pragma unroll
        for (int nt = 0; nt < 8; nt++){
            float* a = acc[mt][nt];
            int r0 = orow + mt*16 + (ln >> 2);
            int c0 = ocol + nt*8 + (ln & 3)*2;
            if (mode == 0){
                #pragma unroll
                for (int q = 0; q < 2; q++){
                    size_t o = (size_t)(r0 + q*8)*N + c0;
                    *(__half2*)(Ch + o) = __halves2half2(
                        __float2half_rn(a[2*q]), __float2half_rn(a[2*q+1]));
                }
            } else if (mode == 1){
                int g = (c0 >> 9) & 3;
                float b0 = bias[c0], b1 = bias[c0+1];
                float v00 = gate_act(a[0] + b0, g), v01 = gate_act(a[1] + b1, g);
                float v10 = gate_act(a[2] + b0, g), v11 = gate_act(a[3] + b1, g);
                *(__half2*)(Ch + (size_t)r0*N + c0) =
                    __halves2half2(__float2half_rn(v00), __float2half_rn(v01));
                *(__half2*)(Ch + (size_t)(r0+8)*N + c0) =
                    __halves2half2(__float2half_rn(v10), __float2half_rn(v11));
            } else {
                *(float2*)(Cf + (size_t)r0*N + c0)     = float2{a[0], a[1]};
                *(float2*)(Cf + (size_t)(r0+8)*N + c0) = float2{a[2], a[3]};
            }
        }
}

// ---------------- scan pass 1: per-chunk (A = prod f, B) — gates pre-activated fp16 ----------------
__global__ void scan_pass1(){
    int blk = blockIdx.x;
    int ch = blk / BH_, bh = blk % BH_;
    int b = bh / NH_, h = bh % NH_;
    int d = threadIdx.x;
    float A = 1.f, Bv = 0.f;
    for (int s = 0; s < CH_; s++){
        int tok = b*L_ + ch*CH_ + s;
        size_t base = (size_t)tok*GN_ + h*(4*HD_) + d;
        float ig = __half2float(g_gates[base]);
        float f  = __half2float(g_gates[base + HD_]);
        float cd = __half2float(g_gates[base + 3*HD_]);
        Bv = f*Bv + ig*cd;
        A *= f;
    }
    g_scanA[ch*BHD_ + bh*HD_ + d] = A;
    g_scanB[ch*BHD_ + bh*HD_ + d] = Bv;
}

// ---------------- scan pass 2: sequential chunk composition ----------------
__global__ void scan_pass2(){
    int idx = blockIdx.x*blockDim.x + threadIdx.x;
    float c = 0.f;
    for (int ch = 0; ch < NCH_; ch++){
        g_carry[ch*BHD_ + idx] = c;
        c = g_scanA[ch*BHD_ + idx]*c + g_scanB[ch*BHD_ + idx];
    }
}

// ---------------- scan pass 3: replay + RMS norm + h (fp16 out), 1 sync/step ----------------
__global__ void scan_pass3(const float* __restrict__ rms_w){
    __shared__ float red[2][16];
    int blk = blockIdx.x;
    int ch = blk / BH_, bh = blk % BH_;
    int b = bh / NH_, h = bh % NH_;
    int d = threadIdx.x;
    int warp = d >> 5, lane = d & 31;
    float c = g_carry[ch*BHD_ + bh*HD_ + d];
    float w = rms_w[d];
    for (int s = 0; s < CH_; s++){
        int tok = b*L_ + ch*CH_ + s;
        size_t base = (size_t)tok*GN_ + h*(4*HD_) + d;
        float ig = __half2float(g_gates[base]);
        float f  = __half2float(g_gates[base + HD_]);
        float og = __half2float(g_gates[base + 2*HD_]);
        float cd = __half2float(g_gates[base + 3*HD_]);
        c = f*c + ig*cd;
        float sq = c*c;
        #pragma unroll
        for (int o = 16; o; o >>= 1) sq += __shfl_xor_sync(0xffffffffu, sq, o);
        int par = s & 1;
        if (!lane) red[par][warp] = sq;
        __syncthreads();
        float tot = 0.f;
        #pragma unroll
        for (int i = 0; i < 16; i++) tot += red[par][i];
        float s_norm = rsqrtf(tot*(1.f/HD_) + EPS_);
        float cn = c * s_norm * w;
        float hv = og * tanhf(cn);
        g_hh[(size_t)tok*HID_ + h*HD_ + d] = __float2half_rn(hv);
    }
}

// ---------------- host side ----------------
typedef CUresult (*PFN_encode_t)(CUtensorMap*, CUtensorMapDataType, cuuint32_t, void*,
                                 const cuuint64_t*, const cuuint64_t*, const cuuint32_t*,
                                 const cuuint32_t*, CUtensorMapInterleave, CUtensorMapSwizzle,
                                 CUtensorMapL2promotion, CUtensorMapFloatOOBfill);

static void enc_map16(PFN_encode_t fn, CUtensorMap* m, void* gaddr, uint64_t rows){
    cuuint64_t dims[2]    = {KROW_, rows};
    cuuint64_t strides[1] = {KROW_ * 2};
    cuuint32_t box[2]     = {64u, 128u};
    cuuint32_t es[2]      = {1u, 1u};
    fn(m, CU_TENSOR_MAP_DATA_TYPE_FLOAT16, 2, gaddr, dims, strides, box, es,
       CU_TENSOR_MAP_INTERLEAVE_NONE, CU_TENSOR_MAP_SWIZZLE_128B,
       CU_TENSOR_MAP_L2_PROMOTION_L2_128B, CU_TENSOR_MAP_FLOAT_OOB_FILL_NONE);
}

extern "C" void kernel_launch(void* const* d_in, const int* in_sizes, int n_in,
                              void* d_out, int out_size){
    const float* x      = (const float*)d_in[0];
    const float* W_in   = (const float*)d_in[1];
    const float* W_gate = (const float*)d_in[2];
    const float* b_gate = (const float*)d_in[3];
    const float* rms_w  = (const float*)d_in[4];
    const float* W_out  = (const float*)d_in[5];

    void *xh, *wih, *wgh, *woh, *xph, *gts, *hh;
    cudaGetSymbolAddress(&xh,  g_xh);
    cudaGetSymbolAddress(&wih, g_Wih);  cudaGetSymbolAddress(&wgh, g_Wgh);
    cudaGetSymbolAddress(&woh, g_Woh);
    cudaGetSymbolAddress(&xph, g_xph);
    cudaGetSymbolAddress(&gts, g_gates);
    cudaGetSymbolAddress(&hh,  g_hh);

    void* pfn = nullptr;
    cudaDriverEntryPointQueryResult qr;
    cudaGetDriverEntryPoint("cuTensorMapEncodeTiled", &pfn, cudaEnableDefault, &qr);
    PFN_encode_t enc = (PFN_encode_t)pfn;

    CUtensorMap mX, mWi, mXp, mWg, mH, mWo;
    enc_map16(enc, &mX,  xh,  NTOK_);
    enc_map16(enc, &mWi, wih, HID_);
    enc_map16(enc, &mXp, xph, NTOK_);
    enc_map16(enc, &mWg, wgh, GN_);
    enc_map16(enc, &mH,  hh,  NTOK_);
    enc_map16(enc, &mWo, woh, DIM_);

    cudaFuncSetAttribute(gemm_f16, cudaFuncAttributeMaxDynamicSharedMemorySize, GSMEM);

    int n4;
    n4 = NTOK_*DIM_/4; to16<<<(n4+255)/256, 256>>>(x,      (__half*)xh,  n4);  // 0
    n4 = HID_*DIM_/4;  to16<<<(n4+255)/256, 256>>>(W_in,   (__half*)wih, n4);  // 1
    n4 = GN_*HID_/4;   to16<<<(n4+255)/256, 256>>>(W_gate, (__half*)wgh, n4);  // 2

    // 3: G1: xp = x @ W_in^T -> fp16   (profiled slot)
    gemm_f16<<<dim3(HID_/128, NTOK_/128), 256, GSMEM>>>(
        mX, mWi, nullptr, nullptr, (__half*)xph, HID_, KROW_/64, 0);

    n4 = DIM_*HID_/4;  to16<<<(n4+255)/256, 256>>>(W_out, (__half*)woh, n4);   // 4

    // G2: gates = act(xp @ W_gate^T + b_gate) -> fp16
    gemm_f16<<<dim3(GN_/128, NTOK_/128), 256, GSMEM>>>(
        mXp, mWg, b_gate, nullptr, (__half*)gts, GN_, KROW_/64, 1);

    // chunked parallel scan
    scan_pass1<<<NCH_*BH_, HD_>>>();
    scan_pass2<<<BHD_/256, 256>>>();
    scan_pass3<<<NCH_*BH_, HD_>>>(rms_w);

    // G3: out = h @ W_out^T -> fp32 to d_out
    gemm_f16<<<dim3(DIM_/128, NTOK_/128), 256, GSMEM>>>(
        mH, mWo, nullptr, (float*)d_out, nullptr, DIM_, KROW_/64, 2);
}